// round 4
// baseline (speedup 1.0000x reference)
#include <cuda_runtime.h>
#include <cuda_bf16.h>
#include <cstdint>

// ---------------- problem constants ----------------
#define VOCAB   50257
#define HDIM    1024
#define SEQ     2048
#define NROWS   4096
#define IGNORE_IDX (-100)

// ---------------- tiling ----------------
#define BM      128
#define BN      256
#define BK      64                 // one 128B swizzle row of bf16
#define NCHUNK  197                // ceil(50257/256)
#define VPAD    (NCHUNK * BN)      // 50432
#define NSPLIT  9                  // grid = 32*9 = 288 CTAs ~ 1.95 waves
#define MTILES  (NROWS / BM)       // 32
#define KB_PER_CHUNK (HDIM / BK)   // 16

#define NTHREADS 512
#define NSTAGE  4
#define A_STAGE_BYTES (BM * 128)           // 16384
#define B_STAGE_BYTES (BN * 128)           // 32768
#define STAGE_BYTES (A_STAGE_BYTES + B_STAGE_BYTES)   // 49152
#define SMEM_DYN (NSTAGE * STAGE_BYTES)    // 196608

#define LOG2E_F 1.4426950408889634f
#define NEG30LOG2E (-43.280851226668906f)
#define LN2_F   0.6931471805599453f
#define CAP_C3 (-3.70370370370e-4f)
#define CAP_C5 (1.64609053498e-7f)

// ---------------- scratch ----------------
__device__ __nv_bfloat16 g_Wb[(size_t)VPAD * HDIM];
__device__ __nv_bfloat16 g_Hb[(size_t)NROWS * HDIM];
__device__ float g_rowsum[NSPLIT][4][NROWS];
__device__ float g_picked[NROWS];

// ---------------- helpers ----------------
__device__ __forceinline__ uint32_t s2u(const void* p) {
    uint32_t a;
    asm("{ .reg .u64 t; cvta.to.shared.u64 t, %1; cvt.u32.u64 %0, t; }" : "=r"(a) : "l"(p));
    return a;
}
__device__ __forceinline__ void cpasync16(uint32_t dst, const void* src) {
    asm volatile("cp.async.cg.shared.global [%0], [%1], 16;" :: "r"(dst), "l"(src));
}
__device__ __forceinline__ uint32_t swz128(uint32_t off) {
    return off ^ ((off >> 3) & 0x70);
}
__device__ __forceinline__ void ldsm_x4(uint32_t* r, uint32_t addr) {
    asm volatile("ldmatrix.sync.aligned.m8n8.x4.shared.b16 {%0,%1,%2,%3}, [%4];"
                 : "=r"(r[0]), "=r"(r[1]), "=r"(r[2]), "=r"(r[3]) : "r"(addr));
}
__device__ __forceinline__ void mma16816(float* d, const uint32_t* a, const uint32_t* b) {
    asm volatile(
        "mma.sync.aligned.m16n8k16.row.col.f32.bf16.bf16.f32 "
        "{%0,%1,%2,%3},{%4,%5,%6,%7},{%8,%9},{%0,%1,%2,%3};\n"
        : "+f"(d[0]), "+f"(d[1]), "+f"(d[2]), "+f"(d[3])
        : "r"(a[0]), "r"(a[1]), "r"(a[2]), "r"(a[3]), "r"(b[0]), "r"(b[1]));
}
__device__ __forceinline__ float ex2f(float x) {
    float r; asm("ex2.approx.f32 %0, %1;" : "=f"(r) : "f"(x)); return r;
}
__device__ __forceinline__ void procc(float x, int gc, int lab, int grow, float& ps) {
    float x2 = x * x;
    float cap = fmaf(x * x2, fmaf(x2, CAP_C5, CAP_C3), x);   // 30*tanh(x/30)
    float e = ex2f(fmaf(cap, LOG2E_F, NEG30LOG2E));          // exp(cap - 30)
    if (gc < VOCAB) ps += e;
    if (gc == lab) g_picked[grow] = cap;
}

// ---------------------------------------------------------------------------
// Kernel 1: fp32 -> bf16 (W padded to VPAD rows with zeros)
// ---------------------------------------------------------------------------
__global__ void convert_kernel(const float* __restrict__ W, const float* __restrict__ Hin) {
    const size_t wq = (size_t)VPAD * HDIM / 4;
    const size_t hq = (size_t)NROWS * HDIM / 4;
    size_t idx = (size_t)blockIdx.x * blockDim.x + threadIdx.x;
    if (idx < wq) {
        size_t e = idx * 4;
        size_t row = e >> 10;
        float4 v;
        if (row < VOCAB) v = *reinterpret_cast<const float4*>(W + e);
        else v = make_float4(0.f, 0.f, 0.f, 0.f);
        __nv_bfloat162 lo = __floats2bfloat162_rn(v.x, v.y);
        __nv_bfloat162 hi = __floats2bfloat162_rn(v.z, v.w);
        *reinterpret_cast<uint2*>(g_Wb + e) =
            make_uint2(*reinterpret_cast<uint32_t*>(&lo), *reinterpret_cast<uint32_t*>(&hi));
    } else if (idx < wq + hq) {
        size_t e = (idx - wq) * 4;
        float4 v = *reinterpret_cast<const float4*>(Hin + e);
        __nv_bfloat162 lo = __floats2bfloat162_rn(v.x, v.y);
        __nv_bfloat162 hi = __floats2bfloat162_rn(v.z, v.w);
        *reinterpret_cast<uint2*>(g_Hb + e) =
            make_uint2(*reinterpret_cast<uint32_t*>(&lo), *reinterpret_cast<uint32_t*>(&hi));
    }
}

// ---------------------------------------------------------------------------
// Kernel 2: fused GEMM + epilogue. 512 threads, 16 warps: 4(M) x 4(N),
// warp tile 32x64 -> 4 warps/SMSP to hide sync/LDSM/scoreboard bubbles.
// ---------------------------------------------------------------------------
extern __shared__ __align__(1024) char dynsmem[];

__global__ void __launch_bounds__(NTHREADS, 1)
lmloss_main(const long long* __restrict__ labels) {
    __shared__ int labs[BM];

    const int tid  = threadIdx.x;
    const int lane = tid & 31;
    const int wid  = tid >> 5;
    const int warpM = wid >> 2;     // 0..3 (32 rows each)
    const int warpN = wid & 3;      // 0..3 (64 cols each)
    const int grp   = lane >> 2;    // 0..7
    const int qp    = lane & 3;     // 0..3

    const int m0 = blockIdx.x * BM;
    const int ys = blockIdx.y;
    const int c0 = (ys * NCHUNK) / NSPLIT;
    const int c1 = ((ys + 1) * NCHUNK) / NSPLIT;
    const int total_kb = (c1 - c0) * KB_PER_CHUNK;

    if (tid < BM) {
        int r = m0 + tid;
        int s = r & (SEQ - 1);
        labs[tid] = (s < SEQ - 1) ? (int)labels[r + 1] : -2;
    }
    __syncthreads();

    const uint32_t smem = s2u(dynsmem);

    // ldmatrix lane address components (permuted-quadrant pattern)
    const uint32_t a_lrow  = (uint32_t)(warpM * 32 + (lane & 15));
    const uint32_t a_lbyte = (uint32_t)((lane >> 4) * 16);
    const uint32_t b_lrow  = (uint32_t)(warpN * 64 + (lane & 7) + (lane >> 4) * 8);
    const uint32_t b_lbyte = (uint32_t)(((lane >> 3) & 1) * 16);

    float acc[2][8][4];
    #pragma unroll
    for (int mi = 0; mi < 2; mi++)
        #pragma unroll
        for (int ni = 0; ni < 8; ni++)
            #pragma unroll
            for (int c = 0; c < 4; c++) acc[mi][ni][c] = 0.f;

    float psum[2][2];
    psum[0][0] = psum[0][1] = psum[1][0] = psum[1][1] = 0.f;

    auto load_stage = [&](int kbg) {
        const int buf = kbg & (NSTAGE - 1);
        const int k0  = (kbg & (KB_PER_CHUNK - 1)) * BK;
        const int n0  = (c0 + (kbg >> 4)) * BN;
        const uint32_t sb = smem + buf * STAGE_BYTES;
        const __nv_bfloat16* Ag = g_Hb + (size_t)m0 * HDIM + k0;
        const __nv_bfloat16* Bg = g_Wb + (size_t)n0 * HDIM + k0;
        #pragma unroll
        for (int i = 0; i < 2; ++i) {           // A: 1024 x 16B chunks
            int c = i * NTHREADS + tid;
            int row = c >> 3, j = c & 7;
            cpasync16(sb + swz128((uint32_t)(row * 128 + j * 16)),
                      Ag + (size_t)row * HDIM + j * 8);
        }
        #pragma unroll
        for (int i = 0; i < 4; ++i) {           // B: 2048 x 16B chunks
            int c = i * NTHREADS + tid;
            int row = c >> 3, j = c & 7;
            cpasync16(sb + A_STAGE_BYTES + swz128((uint32_t)(row * 128 + j * 16)),
                      Bg + (size_t)row * HDIM + j * 8);
        }
    };

    // prologue: 3 stages in flight
    #pragma unroll
    for (int s = 0; s < NSTAGE - 1; ++s) {
        load_stage(s);
        asm volatile("cp.async.commit_group;" ::);
    }

    #pragma unroll 1
    for (int kbg = 0; kbg < total_kb; ++kbg) {
        asm volatile("cp.async.wait_group 2;" ::);
        __syncthreads();   // stage kbg visible; all warps done with stage kbg-1

        if (kbg + NSTAGE - 1 < total_kb) load_stage(kbg + NSTAGE - 1);
        asm volatile("cp.async.commit_group;" ::);   // (possibly empty group)

        const uint32_t sa  = smem + (kbg & (NSTAGE - 1)) * STAGE_BYTES;
        const uint32_t sbb = sa + A_STAGE_BYTES;

        #pragma unroll
        for (int ks = 0; ks < 4; ++ks) {
            uint32_t a[2][4], b[4][4];
            #pragma unroll
            for (int mi = 0; mi < 2; ++mi) {
                uint32_t off = (a_lrow + mi * 16) * 128 + a_lbyte + ks * 32;
                ldsm_x4(a[mi], sa + swz128(off));
            }
            #pragma unroll
            for (int nj = 0; nj < 4; ++nj) {
                uint32_t off = (b_lrow + nj * 16) * 128 + b_lbyte + ks * 32;
                ldsm_x4(b[nj], sbb + swz128(off));
            }
            #pragma unroll
            for (int mi = 0; mi < 2; ++mi)
                #pragma unroll
                for (int nj = 0; nj < 4; ++nj) {
                    mma16816(acc[mi][2 * nj],     a[mi], &b[nj][0]);
                    mma16816(acc[mi][2 * nj + 1], a[mi], &b[nj][2]);
                }
        }

        if ((kbg & (KB_PER_CHUNK - 1)) == KB_PER_CHUNK - 1) {
            // ---- chunk epilogue: softcap + exp + streaming sums ----
            const int n0 = (c0 + (kbg >> 4)) * BN;
            #pragma unroll
            for (int mi = 0; mi < 2; ++mi) {
                int lr0   = warpM * 32 + mi * 16 + grp;
                int lab0  = labs[lr0];
                int lab1  = labs[lr0 + 8];
                int grow0 = m0 + lr0;
                int grow1 = grow0 + 8;
                #pragma unroll
                for (int ni = 0; ni < 8; ++ni) {
                    int gc = n0 + warpN * 64 + ni * 8 + qp * 2;
                    procc(acc[mi][ni][0], gc,     lab0, grow0, psum[mi][0]);
                    procc(acc[mi][ni][1], gc + 1, lab0, grow0, psum[mi][0]);
                    procc(acc[mi][ni][2], gc,     lab1, grow1, psum[mi][1]);
                    procc(acc[mi][ni][3], gc + 1, lab1, grow1, psum[mi][1]);
                    acc[mi][ni][0] = 0.f; acc[mi][ni][1] = 0.f;
                    acc[mi][ni][2] = 0.f; acc[mi][ni][3] = 0.f;
                }
            }
        }
    }

    // ---- quad-reduce partial sums, write scratch ----
    #pragma unroll
    for (int mi = 0; mi < 2; ++mi) {
        #pragma unroll
        for (int h = 0; h < 2; ++h) {
            float p = psum[mi][h];
            p += __shfl_xor_sync(0xffffffff, p, 1);
            p += __shfl_xor_sync(0xffffffff, p, 2);
            if (qp == 0) {
                int r = m0 + warpM * 32 + mi * 16 + grp + h * 8;
                g_rowsum[ys][warpN][r] = p;
            }
        }
    }
}

// ---------------------------------------------------------------------------
// Kernel 3: finalize
// ---------------------------------------------------------------------------
__global__ void finalize_kernel(const long long* __restrict__ labels, float* __restrict__ out) {
    __shared__ float sce[256];
    __shared__ float szz[256];
    __shared__ int   scn[256];
    const int tid = threadIdx.x;
    float ce = 0.f, zz = 0.f;
    int cnt = 0;
    for (int r = tid; r < NROWS; r += 256) {
        int s = r & (SEQ - 1);
        if (s == SEQ - 1) continue;
        long long lab = labels[r + 1];
        if (lab == IGNORE_IDX) continue;
        float Ssum = 0.f;
        #pragma unroll
        for (int y = 0; y < NSPLIT; ++y)
            #pragma unroll
            for (int w = 0; w < 4; ++w)
                Ssum += g_rowsum[y][w][r];
        float l2;
        asm("lg2.approx.f32 %0, %1;" : "=f"(l2) : "f"(Ssum));
        float logz = fmaf(l2, LN2_F, 30.0f);
        ce += logz - g_picked[r];
        zz += logz * logz;
        cnt++;
    }
    sce[tid] = ce; szz[tid] = zz; scn[tid] = cnt;
    __syncthreads();
    for (int off = 128; off > 0; off >>= 1) {
        if (tid < off) {
            sce[tid] += sce[tid + off];
            szz[tid] += szz[tid + off];
            scn[tid] += scn[tid + off];
        }
        __syncthreads();
    }
    if (tid == 0) {
        float n = (float)(scn[0] > 0 ? scn[0] : 1);
        out[0] = sce[0] / n + 1e-4f * (szz[0] / n);
    }
}

// ---------------------------------------------------------------------------
// Launch
// ---------------------------------------------------------------------------
extern "C" void kernel_launch(void* const* d_in, const int* in_sizes, int n_in,
                              void* d_out, int out_size) {
    (void)in_sizes; (void)n_in; (void)out_size;
    const float*     hid    = (const float*)d_in[0];
    const float*     W      = (const float*)d_in[1];
    const long long* labels = (const long long*)d_in[2];
    float*           out    = (float*)d_out;

    const size_t wq = (size_t)VPAD * HDIM / 4;
    const size_t hq = (size_t)NROWS * HDIM / 4;
    const int total = (int)(wq + hq);
    convert_kernel<<<(total + 255) / 256, 256>>>(W, hid);

    cudaFuncSetAttribute(lmloss_main, cudaFuncAttributeMaxDynamicSharedMemorySize, SMEM_DYN);
    dim3 grid(MTILES, NSPLIT);
    lmloss_main<<<grid, NTHREADS, SMEM_DYN>>>(labels);

    finalize_kernel<<<1, 256>>>(labels, out);
}

// round 5
// speedup vs baseline: 1.0294x; 1.0294x over previous
#include <cuda_runtime.h>
#include <cuda_fp16.h>
#include <cstdint>

// ---------------- problem constants ----------------
#define VOCAB   50257
#define HDIM    1024
#define SEQ     2048
#define NROWS   4096
#define IGNORE_IDX (-100)

// ---------------- tiling ----------------
#define BM      128
#define BN      256
#define BK      64                 // one 128B swizzle row of f16
#define NCHUNK  197                // ceil(50257/256)
#define VPAD    (NCHUNK * BN)      // 50432
#define NSPLIT  9                  // grid = 32*9 = 288 CTAs ~ 1.95 waves
#define MTILES  (NROWS / BM)       // 32
#define KB_PER_CHUNK (HDIM / BK)   // 16

#define NTHREADS 256
#define NSTAGE  4
#define A_STAGE_BYTES (BM * 128)           // 16384
#define B_STAGE_BYTES (BN * 128)           // 32768
#define STAGE_BYTES (A_STAGE_BYTES + B_STAGE_BYTES)   // 49152
#define SMEM_DYN (NSTAGE * STAGE_BYTES)    // 196608

#define LOG2E_F 1.4426950408889634f
#define NEG30LOG2E (-43.280851226668906f)
#define LN2_F   0.6931471805599453f
#define CAP_C3 (-3.70370370370e-4f)
#define CAP_C5 (1.64609053498e-7f)

// ---------------- scratch ----------------
__device__ __half g_Wh[(size_t)VPAD * HDIM];
__device__ __half g_Hh[(size_t)NROWS * HDIM];
__device__ float g_rowsum[NSPLIT][4][NROWS];
__device__ float g_picked[NROWS];

// ---------------- helpers ----------------
__device__ __forceinline__ uint32_t s2u(const void* p) {
    uint32_t a;
    asm("{ .reg .u64 t; cvta.to.shared.u64 t, %1; cvt.u32.u64 %0, t; }" : "=r"(a) : "l"(p));
    return a;
}
__device__ __forceinline__ void cpasync16(uint32_t dst, const void* src) {
    asm volatile("cp.async.cg.shared.global [%0], [%1], 16;" :: "r"(dst), "l"(src));
}
__device__ __forceinline__ uint32_t swz128(uint32_t off) {
    return off ^ ((off >> 3) & 0x70);
}
__device__ __forceinline__ void ldsm_x4(uint32_t* r, uint32_t addr) {
    asm volatile("ldmatrix.sync.aligned.m8n8.x4.shared.b16 {%0,%1,%2,%3}, [%4];"
                 : "=r"(r[0]), "=r"(r[1]), "=r"(r[2]), "=r"(r[3]) : "r"(addr));
}
// f16 accumulate: d = {row grp cols 2q..2q+1, row grp+8 cols 2q..2q+1} as 2x f16x2
__device__ __forceinline__ void mma16816_f16(uint32_t* d, const uint32_t* a, const uint32_t* b) {
    asm volatile(
        "mma.sync.aligned.m16n8k16.row.col.f16.f16.f16.f16 "
        "{%0,%1},{%2,%3,%4,%5},{%6,%7},{%0,%1};\n"
        : "+r"(d[0]), "+r"(d[1])
        : "r"(a[0]), "r"(a[1]), "r"(a[2]), "r"(a[3]), "r"(b[0]), "r"(b[1]));
}
__device__ __forceinline__ float ex2f(float x) {
    float r; asm("ex2.approx.f32 %0, %1;" : "=f"(r) : "f"(x)); return r;
}
__device__ __forceinline__ void procc(float x, int gc, int lab, int grow, float& ps) {
    float x2 = x * x;
    float cap = fmaf(x * x2, fmaf(x2, CAP_C5, CAP_C3), x);   // 30*tanh(x/30)
    float e = ex2f(fmaf(cap, LOG2E_F, NEG30LOG2E));          // exp(cap - 30)
    if (gc < VOCAB) ps += e;
    if (gc == lab) g_picked[grow] = cap;
}

// ---------------------------------------------------------------------------
// Kernel 1: fp32 -> f16 (W padded to VPAD rows with zeros)
// ---------------------------------------------------------------------------
__global__ void convert_kernel(const float* __restrict__ W, const float* __restrict__ Hin) {
    const size_t wq = (size_t)VPAD * HDIM / 4;
    const size_t hq = (size_t)NROWS * HDIM / 4;
    size_t idx = (size_t)blockIdx.x * blockDim.x + threadIdx.x;
    if (idx < wq) {
        size_t e = idx * 4;
        size_t row = e >> 10;
        float4 v;
        if (row < VOCAB) v = *reinterpret_cast<const float4*>(W + e);
        else v = make_float4(0.f, 0.f, 0.f, 0.f);
        __half2 lo = __floats2half2_rn(v.x, v.y);
        __half2 hi = __floats2half2_rn(v.z, v.w);
        *reinterpret_cast<uint2*>(g_Wh + e) =
            make_uint2(*reinterpret_cast<uint32_t*>(&lo), *reinterpret_cast<uint32_t*>(&hi));
    } else if (idx < wq + hq) {
        size_t e = (idx - wq) * 4;
        float4 v = *reinterpret_cast<const float4*>(Hin + e);
        __half2 lo = __floats2half2_rn(v.x, v.y);
        __half2 hi = __floats2half2_rn(v.z, v.w);
        *reinterpret_cast<uint2*>(g_Hh + e) =
            make_uint2(*reinterpret_cast<uint32_t*>(&lo), *reinterpret_cast<uint32_t*>(&hi));
    }
}

// ---------------------------------------------------------------------------
// Kernel 2: fused GEMM (f16 accumulate) + epilogue.
// 256 threads, 8 warps: 2(M) x 4(N), warp tile 64x64.
// ---------------------------------------------------------------------------
extern __shared__ __align__(1024) char dynsmem[];

__global__ void __launch_bounds__(NTHREADS, 1)
lmloss_main(const long long* __restrict__ labels) {
    __shared__ int labs[BM];

    const int tid  = threadIdx.x;
    const int lane = tid & 31;
    const int wid  = tid >> 5;
    const int warpM = wid >> 2;     // 0..1
    const int warpN = wid & 3;      // 0..3
    const int grp   = lane >> 2;    // 0..7
    const int qp    = lane & 3;     // 0..3

    const int m0 = blockIdx.x * BM;
    const int ys = blockIdx.y;
    const int c0 = (ys * NCHUNK) / NSPLIT;
    const int c1 = ((ys + 1) * NCHUNK) / NSPLIT;
    const int total_kb = (c1 - c0) * KB_PER_CHUNK;

    if (tid < BM) {
        int r = m0 + tid;
        int s = r & (SEQ - 1);
        labs[tid] = (s < SEQ - 1) ? (int)labels[r + 1] : -2;
    }
    __syncthreads();

    const uint32_t smem = s2u(dynsmem);

    const uint32_t a_lrow  = (uint32_t)(warpM * 64 + (lane & 15));
    const uint32_t a_lbyte = (uint32_t)((lane >> 4) * 16);
    const uint32_t b_lrow  = (uint32_t)(warpN * 64 + (lane & 7) + (lane >> 4) * 8);
    const uint32_t b_lbyte = (uint32_t)(((lane >> 3) & 1) * 16);

    // f16x2 accumulators: acc[mi][ni][0] = row grp, [1] = row grp+8 (cols 2qp..2qp+1)
    uint32_t acc[4][8][2];
    #pragma unroll
    for (int mi = 0; mi < 4; mi++)
        #pragma unroll
        for (int ni = 0; ni < 8; ni++) { acc[mi][ni][0] = 0u; acc[mi][ni][1] = 0u; }

    float psum[4][2];
    #pragma unroll
    for (int i = 0; i < 4; i++) { psum[i][0] = 0.f; psum[i][1] = 0.f; }

    auto load_stage = [&](int kbg) {
        const int buf = kbg & (NSTAGE - 1);
        const int k0  = (kbg & (KB_PER_CHUNK - 1)) * BK;
        const int n0  = (c0 + (kbg >> 4)) * BN;
        const uint32_t sb = smem + buf * STAGE_BYTES;
        const __half* Ag = g_Hh + (size_t)m0 * HDIM + k0;
        const __half* Bg = g_Wh + (size_t)n0 * HDIM + k0;
        #pragma unroll
        for (int i = 0; i < 4; ++i) {           // A: 1024 x 16B chunks
            int c = i * NTHREADS + tid;
            int row = c >> 3, j = c & 7;
            cpasync16(sb + swz128((uint32_t)(row * 128 + j * 16)),
                      Ag + (size_t)row * HDIM + j * 8);
        }
        #pragma unroll
        for (int i = 0; i < 8; ++i) {           // B: 2048 x 16B chunks
            int c = i * NTHREADS + tid;
            int row = c >> 3, j = c & 7;
            cpasync16(sb + A_STAGE_BYTES + swz128((uint32_t)(row * 128 + j * 16)),
                      Bg + (size_t)row * HDIM + j * 8);
        }
    };

    // prologue: 3 stages in flight
    #pragma unroll
    for (int s = 0; s < NSTAGE - 1; ++s) {
        load_stage(s);
        asm volatile("cp.async.commit_group;" ::);
    }

    #pragma unroll 1
    for (int kbg = 0; kbg < total_kb; ++kbg) {
        asm volatile("cp.async.wait_group 2;" ::);
        __syncthreads();

        if (kbg + NSTAGE - 1 < total_kb) load_stage(kbg + NSTAGE - 1);
        asm volatile("cp.async.commit_group;" ::);

        const uint32_t sa  = smem + (kbg & (NSTAGE - 1)) * STAGE_BYTES;
        const uint32_t sbb = sa + A_STAGE_BYTES;

        #pragma unroll
        for (int ks = 0; ks < 4; ++ks) {
            uint32_t a[4][4], b[4][4];
            #pragma unroll
            for (int mi = 0; mi < 4; ++mi) {
                uint32_t off = (a_lrow + mi * 16) * 128 + a_lbyte + ks * 32;
                ldsm_x4(a[mi], sa + swz128(off));
            }
            #pragma unroll
            for (int nj = 0; nj < 4; ++nj) {
                uint32_t off = (b_lrow + nj * 16) * 128 + b_lbyte + ks * 32;
                ldsm_x4(b[nj], sbb + swz128(off));
            }
            #pragma unroll
            for (int mi = 0; mi < 4; ++mi)
                #pragma unroll
                for (int nj = 0; nj < 4; ++nj) {
                    mma16816_f16(acc[mi][2 * nj],     a[mi], &b[nj][0]);
                    mma16816_f16(acc[mi][2 * nj + 1], a[mi], &b[nj][2]);
                }
        }

        if ((kbg & (KB_PER_CHUNK - 1)) == KB_PER_CHUNK - 1) {
            // ---- chunk epilogue: unpack f16x2, softcap + exp + streaming sums ----
            const int n0 = (c0 + (kbg >> 4)) * BN;
            #pragma unroll
            for (int mi = 0; mi < 4; ++mi) {
                int lr0   = warpM * 64 + mi * 16 + grp;
                int lab0  = labs[lr0];
                int lab1  = labs[lr0 + 8];
                int grow0 = m0 + lr0;
                int grow1 = grow0 + 8;
                #pragma unroll
                for (int ni = 0; ni < 8; ++ni) {
                    int gc = n0 + warpN * 64 + ni * 8 + qp * 2;
                    __half2 h0 = *reinterpret_cast<__half2*>(&acc[mi][ni][0]);
                    __half2 h1 = *reinterpret_cast<__half2*>(&acc[mi][ni][1]);
                    float2 f0 = __half22float2(h0);
                    float2 f1 = __half22float2(h1);
                    procc(f0.x, gc,     lab0, grow0, psum[mi][0]);
                    procc(f0.y, gc + 1, lab0, grow0, psum[mi][0]);
                    procc(f1.x, gc,     lab1, grow1, psum[mi][1]);
                    procc(f1.y, gc + 1, lab1, grow1, psum[mi][1]);
                    acc[mi][ni][0] = 0u; acc[mi][ni][1] = 0u;
                }
            }
        }
    }

    // ---- quad-reduce partial sums, write scratch ----
    #pragma unroll
    for (int mi = 0; mi < 4; ++mi) {
        #pragma unroll
        for (int h = 0; h < 2; ++h) {
            float p = psum[mi][h];
            p += __shfl_xor_sync(0xffffffff, p, 1);
            p += __shfl_xor_sync(0xffffffff, p, 2);
            if (qp == 0) {
                int r = m0 + warpM * 64 + mi * 16 + grp + h * 8;
                g_rowsum[ys][warpN][r] = p;
            }
        }
    }
}

// ---------------------------------------------------------------------------
// Kernel 3: finalize
// ---------------------------------------------------------------------------
__global__ void finalize_kernel(const long long* __restrict__ labels, float* __restrict__ out) {
    __shared__ float sce[256];
    __shared__ float szz[256];
    __shared__ int   scn[256];
    const int tid = threadIdx.x;
    float ce = 0.f, zz = 0.f;
    int cnt = 0;
    for (int r = tid; r < NROWS; r += 256) {
        int s = r & (SEQ - 1);
        if (s == SEQ - 1) continue;
        long long lab = labels[r + 1];
        if (lab == IGNORE_IDX) continue;
        float Ssum = 0.f;
        #pragma unroll
        for (int y = 0; y < NSPLIT; ++y)
            #pragma unroll
            for (int w = 0; w < 4; ++w)
                Ssum += g_rowsum[y][w][r];
        float l2;
        asm("lg2.approx.f32 %0, %1;" : "=f"(l2) : "f"(Ssum));
        float logz = fmaf(l2, LN2_F, 30.0f);
        ce += logz - g_picked[r];
        zz += logz * logz;
        cnt++;
    }
    sce[tid] = ce; szz[tid] = zz; scn[tid] = cnt;
    __syncthreads();
    for (int off = 128; off > 0; off >>= 1) {
        if (tid < off) {
            sce[tid] += sce[tid + off];
            szz[tid] += szz[tid + off];
            scn[tid] += scn[tid + off];
        }
        __syncthreads();
    }
    if (tid == 0) {
        float n = (float)(scn[0] > 0 ? scn[0] : 1);
        out[0] = sce[0] / n + 1e-4f * (szz[0] / n);
    }
}

// ---------------------------------------------------------------------------
// Launch
// ---------------------------------------------------------------------------
extern "C" void kernel_launch(void* const* d_in, const int* in_sizes, int n_in,
                              void* d_out, int out_size) {
    (void)in_sizes; (void)n_in; (void)out_size;
    const float*     hid    = (const float*)d_in[0];
    const float*     W      = (const float*)d_in[1];
    const long long* labels = (const long long*)d_in[2];
    float*           out    = (float*)d_out;

    const size_t wq = (size_t)VPAD * HDIM / 4;
    const size_t hq = (size_t)NROWS * HDIM / 4;
    const int total = (int)(wq + hq);
    convert_kernel<<<(total + 255) / 256, 256>>>(W, hid);

    cudaFuncSetAttribute(lmloss_main, cudaFuncAttributeMaxDynamicSharedMemorySize, SMEM_DYN);
    dim3 grid(MTILES, NSPLIT);
    lmloss_main<<<grid, NTHREADS, SMEM_DYN>>>(labels);

    finalize_kernel<<<1, 256>>>(labels, out);
}

// round 6
// speedup vs baseline: 1.0722x; 1.0415x over previous
#include <cuda_runtime.h>
#include <cuda_fp16.h>
#include <cstdint>

// ---------------- problem constants ----------------
#define VOCAB   50257
#define HDIM    1024
#define SEQ     2048
#define NROWS   4096
#define IGNORE_IDX (-100)

// ---------------- tiling ----------------
#define BM      128
#define BN      256
#define BK      64                 // one 128B swizzle row of f16
#define NCHUNK  197                // ceil(50257/256)
#define VPAD    (NCHUNK * BN)      // 50432
#define NSPLIT  9                  // grid = 32*9 = 288 CTAs, 2 CTAs/SM -> ~0.97 wave
#define MTILES  (NROWS / BM)       // 32
#define KB_PER_CHUNK (HDIM / BK)   // 16

#define NTHREADS 256
#define NSTAGE  2
#define A_STAGE_BYTES (BM * 128)           // 16384
#define B_STAGE_BYTES (BN * 128)           // 32768
#define STAGE_BYTES (A_STAGE_BYTES + B_STAGE_BYTES)   // 49152
#define SMEM_DYN (NSTAGE * STAGE_BYTES)    // 98304 -> 2 CTAs/SM

#define LOG2E_F 1.4426950408889634f
#define NEG30LOG2E (-43.280851226668906f)
#define LN2_F   0.6931471805599453f
#define CAP_C3 (-3.70370370370e-4f)
#define CAP_C5 (1.64609053498e-7f)

// ---------------- scratch ----------------
__device__ __half g_Wh[(size_t)VPAD * HDIM];
__device__ __half g_Hh[(size_t)NROWS * HDIM];
__device__ float g_rowsum[NSPLIT][4][NROWS];
__device__ float g_picked[NROWS];

// ---------------- helpers ----------------
__device__ __forceinline__ uint32_t s2u(const void* p) {
    uint32_t a;
    asm("{ .reg .u64 t; cvta.to.shared.u64 t, %1; cvt.u32.u64 %0, t; }" : "=r"(a) : "l"(p));
    return a;
}
__device__ __forceinline__ void cpasync16(uint32_t dst, const void* src) {
    asm volatile("cp.async.cg.shared.global [%0], [%1], 16;" :: "r"(dst), "l"(src));
}
__device__ __forceinline__ uint32_t swz128(uint32_t off) {
    return off ^ ((off >> 3) & 0x70);
}
__device__ __forceinline__ void ldsm_x4(uint32_t* r, uint32_t addr) {
    asm volatile("ldmatrix.sync.aligned.m8n8.x4.shared.b16 {%0,%1,%2,%3}, [%4];"
                 : "=r"(r[0]), "=r"(r[1]), "=r"(r[2]), "=r"(r[3]) : "r"(addr));
}
// f16 accumulate
__device__ __forceinline__ void mma16816_f16(uint32_t* d, const uint32_t* a, const uint32_t* b) {
    asm volatile(
        "mma.sync.aligned.m16n8k16.row.col.f16.f16.f16.f16 "
        "{%0,%1},{%2,%3,%4,%5},{%6,%7},{%0,%1};\n"
        : "+r"(d[0]), "+r"(d[1])
        : "r"(a[0]), "r"(a[1]), "r"(a[2]), "r"(a[3]), "r"(b[0]), "r"(b[1]));
}
__device__ __forceinline__ float ex2f(float x) {
    float r; asm("ex2.approx.f32 %0, %1;" : "=f"(r) : "f"(x)); return r;
}
__device__ __forceinline__ void procc(float x, int gc, int lab, int grow, float& ps) {
    float x2 = x * x;
    float cap = fmaf(x * x2, fmaf(x2, CAP_C5, CAP_C3), x);   // 30*tanh(x/30)
    float e = ex2f(fmaf(cap, LOG2E_F, NEG30LOG2E));          // exp(cap - 30)
    if (gc < VOCAB) ps += e;
    if (gc == lab) g_picked[grow] = cap;
}

// ---------------------------------------------------------------------------
// Kernel 1: fp32 -> f16 (W padded to VPAD rows with zeros)
// ---------------------------------------------------------------------------
__global__ void convert_kernel(const float* __restrict__ W, const float* __restrict__ Hin) {
    const size_t wq = (size_t)VPAD * HDIM / 4;
    const size_t hq = (size_t)NROWS * HDIM / 4;
    size_t idx = (size_t)blockIdx.x * blockDim.x + threadIdx.x;
    if (idx < wq) {
        size_t e = idx * 4;
        size_t row = e >> 10;
        float4 v;
        if (row < VOCAB) v = *reinterpret_cast<const float4*>(W + e);
        else v = make_float4(0.f, 0.f, 0.f, 0.f);
        __half2 lo = __floats2half2_rn(v.x, v.y);
        __half2 hi = __floats2half2_rn(v.z, v.w);
        *reinterpret_cast<uint2*>(g_Wh + e) =
            make_uint2(*reinterpret_cast<uint32_t*>(&lo), *reinterpret_cast<uint32_t*>(&hi));
    } else if (idx < wq + hq) {
        size_t e = (idx - wq) * 4;
        float4 v = *reinterpret_cast<const float4*>(Hin + e);
        __half2 lo = __floats2half2_rn(v.x, v.y);
        __half2 hi = __floats2half2_rn(v.z, v.w);
        *reinterpret_cast<uint2*>(g_Hh + e) =
            make_uint2(*reinterpret_cast<uint32_t*>(&lo), *reinterpret_cast<uint32_t*>(&hi));
    }
}

// ---------------------------------------------------------------------------
// Kernel 2: fused GEMM (f16 acc) + epilogue. 256 thr, 8 warps 2(M)x4(N),
// warp tile 64x64, 2-stage cp.async, 2 CTAs/SM for bubble-filling.
// ---------------------------------------------------------------------------
extern __shared__ __align__(1024) char dynsmem[];

__global__ void __launch_bounds__(NTHREADS, 2)
lmloss_main(const long long* __restrict__ labels) {
    __shared__ int labs[BM];

    const int tid  = threadIdx.x;
    const int lane = tid & 31;
    const int wid  = tid >> 5;
    const int warpM = wid >> 2;     // 0..1
    const int warpN = wid & 3;      // 0..3
    const int grp   = lane >> 2;    // 0..7
    const int qp    = lane & 3;     // 0..3

    const int m0 = blockIdx.x * BM;
    const int ys = blockIdx.y;
    const int c0 = (ys * NCHUNK) / NSPLIT;
    const int c1 = ((ys + 1) * NCHUNK) / NSPLIT;
    const int total_kb = (c1 - c0) * KB_PER_CHUNK;

    if (tid < BM) {
        int r = m0 + tid;
        int s = r & (SEQ - 1);
        labs[tid] = (s < SEQ - 1) ? (int)labels[r + 1] : -2;
    }
    __syncthreads();

    const uint32_t smem = s2u(dynsmem);

    const uint32_t a_lrow  = (uint32_t)(warpM * 64 + (lane & 15));
    const uint32_t a_lbyte = (uint32_t)((lane >> 4) * 16);
    const uint32_t b_lrow  = (uint32_t)(warpN * 64 + (lane & 7) + (lane >> 4) * 8);
    const uint32_t b_lbyte = (uint32_t)(((lane >> 3) & 1) * 16);

    // f16x2 accumulators
    uint32_t acc[4][8][2];
    #pragma unroll
    for (int mi = 0; mi < 4; mi++)
        #pragma unroll
        for (int ni = 0; ni < 8; ni++) { acc[mi][ni][0] = 0u; acc[mi][ni][1] = 0u; }

    float psum[4][2];
    #pragma unroll
    for (int i = 0; i < 4; i++) { psum[i][0] = 0.f; psum[i][1] = 0.f; }

    auto load_stage = [&](int kbg) {
        const int buf = kbg & (NSTAGE - 1);
        const int k0  = (kbg & (KB_PER_CHUNK - 1)) * BK;
        const int n0  = (c0 + (kbg >> 4)) * BN;
        const uint32_t sb = smem + buf * STAGE_BYTES;
        const __half* Ag = g_Hh + (size_t)m0 * HDIM + k0;
        const __half* Bg = g_Wh + (size_t)n0 * HDIM + k0;
        #pragma unroll
        for (int i = 0; i < 4; ++i) {           // A: 1024 x 16B chunks
            int c = i * NTHREADS + tid;
            int row = c >> 3, j = c & 7;
            cpasync16(sb + swz128((uint32_t)(row * 128 + j * 16)),
                      Ag + (size_t)row * HDIM + j * 8);
        }
        #pragma unroll
        for (int i = 0; i < 8; ++i) {           // B: 2048 x 16B chunks
            int c = i * NTHREADS + tid;
            int row = c >> 3, j = c & 7;
            cpasync16(sb + A_STAGE_BYTES + swz128((uint32_t)(row * 128 + j * 16)),
                      Bg + (size_t)row * HDIM + j * 8);
        }
    };

    // prologue: both stages in flight
    load_stage(0);
    asm volatile("cp.async.commit_group;" ::);
    load_stage(1);
    asm volatile("cp.async.commit_group;" ::);

    #pragma unroll 1
    for (int kbg = 0; kbg < total_kb; ++kbg) {
        asm volatile("cp.async.wait_group 1;" ::);   // stage kbg landed
        __syncthreads();

        const uint32_t sa  = smem + (kbg & (NSTAGE - 1)) * STAGE_BYTES;
        const uint32_t sbb = sa + A_STAGE_BYTES;

        #pragma unroll
        for (int ks = 0; ks < 4; ++ks) {
            uint32_t a[4][4], b[4][4];
            #pragma unroll
            for (int mi = 0; mi < 4; ++mi) {
                uint32_t off = (a_lrow + mi * 16) * 128 + a_lbyte + ks * 32;
                ldsm_x4(a[mi], sa + swz128(off));
            }
            #pragma unroll
            for (int nj = 0; nj < 4; ++nj) {
                uint32_t off = (b_lrow + nj * 16) * 128 + b_lbyte + ks * 32;
                ldsm_x4(b[nj], sbb + swz128(off));
            }
            #pragma unroll
            for (int mi = 0; mi < 4; ++mi)
                #pragma unroll
                for (int nj = 0; nj < 4; ++nj) {
                    mma16816_f16(acc[mi][2 * nj],     a[mi], &b[nj][0]);
                    mma16816_f16(acc[mi][2 * nj + 1], a[mi], &b[nj][2]);
                }
        }

        __syncthreads();   // all warps done reading buf (kbg&1)
        if (kbg + NSTAGE < total_kb) load_stage(kbg + NSTAGE);
        asm volatile("cp.async.commit_group;" ::);   // keep group count uniform

        if ((kbg & (KB_PER_CHUNK - 1)) == KB_PER_CHUNK - 1) {
            // ---- chunk epilogue (regs only; overlaps in-flight cp.async) ----
            const int n0 = (c0 + (kbg >> 4)) * BN;
            #pragma unroll
            for (int mi = 0; mi < 4; ++mi) {
                int lr0   = warpM * 64 + mi * 16 + grp;
                int lab0  = labs[lr0];
                int lab1  = labs[lr0 + 8];
                int grow0 = m0 + lr0;
                int grow1 = grow0 + 8;
                #pragma unroll
                for (int ni = 0; ni < 8; ++ni) {
                    int gc = n0 + warpN * 64 + ni * 8 + qp * 2;
                    __half2 h0 = *reinterpret_cast<__half2*>(&acc[mi][ni][0]);
                    __half2 h1 = *reinterpret_cast<__half2*>(&acc[mi][ni][1]);
                    float2 f0 = __half22float2(h0);
                    float2 f1 = __half22float2(h1);
                    procc(f0.x, gc,     lab0, grow0, psum[mi][0]);
                    procc(f0.y, gc + 1, lab0, grow0, psum[mi][0]);
                    procc(f1.x, gc,     lab1, grow1, psum[mi][1]);
                    procc(f1.y, gc + 1, lab1, grow1, psum[mi][1]);
                    acc[mi][ni][0] = 0u; acc[mi][ni][1] = 0u;
                }
            }
        }
    }

    // ---- quad-reduce partial sums, write scratch ----
    #pragma unroll
    for (int mi = 0; mi < 4; ++mi) {
        #pragma unroll
        for (int h = 0; h < 2; ++h) {
            float p = psum[mi][h];
            p += __shfl_xor_sync(0xffffffff, p, 1);
            p += __shfl_xor_sync(0xffffffff, p, 2);
            if (qp == 0) {
                int r = m0 + warpM * 64 + mi * 16 + grp + h * 8;
                g_rowsum[ys][warpN][r] = p;
            }
        }
    }
}

// ---------------------------------------------------------------------------
// Kernel 3: finalize
// ---------------------------------------------------------------------------
__global__ void finalize_kernel(const long long* __restrict__ labels, float* __restrict__ out) {
    __shared__ float sce[256];
    __shared__ float szz[256];
    __shared__ int   scn[256];
    const int tid = threadIdx.x;
    float ce = 0.f, zz = 0.f;
    int cnt = 0;
    for (int r = tid; r < NROWS; r += 256) {
        int s = r & (SEQ - 1);
        if (s == SEQ - 1) continue;
        long long lab = labels[r + 1];
        if (lab == IGNORE_IDX) continue;
        float Ssum = 0.f;
        #pragma unroll
        for (int y = 0; y < NSPLIT; ++y)
            #pragma unroll
            for (int w = 0; w < 4; ++w)
                Ssum += g_rowsum[y][w][r];
        float l2;
        asm("lg2.approx.f32 %0, %1;" : "=f"(l2) : "f"(Ssum));
        float logz = fmaf(l2, LN2_F, 30.0f);
        ce += logz - g_picked[r];
        zz += logz * logz;
        cnt++;
    }
    sce[tid] = ce; szz[tid] = zz; scn[tid] = cnt;
    __syncthreads();
    for (int off = 128; off > 0; off >>= 1) {
        if (tid < off) {
            sce[tid] += sce[tid + off];
            szz[tid] += szz[tid + off];
            scn[tid] += scn[tid + off];
        }
        __syncthreads();
    }
    if (tid == 0) {
        float n = (float)(scn[0] > 0 ? scn[0] : 1);
        out[0] = sce[0] / n + 1e-4f * (szz[0] / n);
    }
}

// ---------------------------------------------------------------------------
// Launch
// ---------------------------------------------------------------------------
extern "C" void kernel_launch(void* const* d_in, const int* in_sizes, int n_in,
                              void* d_out, int out_size) {
    (void)in_sizes; (void)n_in; (void)out_size;
    const float*     hid    = (const float*)d_in[0];
    const float*     W      = (const float*)d_in[1];
    const long long* labels = (const long long*)d_in[2];
    float*           out    = (float*)d_out;

    const size_t wq = (size_t)VPAD * HDIM / 4;
    const size_t hq = (size_t)NROWS * HDIM / 4;
    const int total = (int)(wq + hq);
    convert_kernel<<<(total + 255) / 256, 256>>>(W, hid);

    cudaFuncSetAttribute(lmloss_main, cudaFuncAttributeMaxDynamicSharedMemorySize, SMEM_DYN);
    dim3 grid(MTILES, NSPLIT);
    lmloss_main<<<grid, NTHREADS, SMEM_DYN>>>(labels);

    finalize_kernel<<<1, 256>>>(labels, out);
}